// round 14
// baseline (speedup 1.0000x reference)
#include <cuda_runtime.h>
#include <cstdint>
#include <math.h>

// Problem constants
#define Bp   4096
#define Dd   19
#define Ff   64
#define NCc  256
#define HIDh 32
#define SQq  16
#define Nn   (Bp + NCc)
#define PD   20            // padded row stride (19 + 1 zero pad)
#define PD4  5             // PD/4 (float4 granules)

// Tiling: task = (jt, it8); warp = (center in group of 8, j-half)
#define JT   128            // j per tile
#define NJT  (Nn / JT)      // 34
#define NPJT (Bp / JT)      // 32 patient-only tiles
#define IT   8              // centers per task
#define NIT  (NCc / IT)     // 32
#define NTASK (NJT * NIT)   // 1088
#define NSLOT (NJT * 2)     // 68 partial-y slots (jt, half)
#define TCHUNKS (JT * PD4 * 2)   // 1280 x 16B chunks per tile (x + e)

// Persistent grid
#define NBLK 148
#define NTHR 512
#define NT_ALL (NBLK * NTHR)       // 75776

// Output offsets (floats)
#define OUT_GS  0
#define OUT_GE  (Bp * Dd)
#define OUT_GPE ((Bp + NCc) * Dd)
#define OUT_GL  (((2 * Bp) + NCc) * Dd)

typedef unsigned long long u64;

// -------- device scratch (no allocations allowed) --------
__device__ float4 g_x4[Nn * PD4];
__device__ float4 g_e4[Nn * PD4];
__device__ float  g_party[NSLOT * NCc * PD];  // y-partials per (slot, center)
__device__ u64    g_key[NCc * Bp];            // [center][patient] denom keys
__device__ float  g_ge[NCc * Dd];
__device__ float  g_sc[NCc * Dd];

// grid barrier state (zero-init at load; returns to steady state each run)
__device__ unsigned g_cnt[8];
__device__ unsigned g_cnt_root;
__device__ volatile unsigned g_bar_sense;
__device__ unsigned g_task;                 // work-stealing ticket

// Two-level sense-reversal barrier: 8 group counters -> root counter.
__device__ __forceinline__ void grid_barrier(unsigned* sense0) {
    __syncthreads();
    if (threadIdx.x == 0) {
        unsigned next = *sense0 ^ 1u;
        __threadfence();                       // publish this block's writes
        int g = blockIdx.x & 7;
        unsigned gsz = (g < 4) ? 19u : 18u;    // 148 = 4*19 + 4*18
        if (atomicAdd(&g_cnt[g], 1u) == gsz - 1u) {
            if (atomicAdd(&g_cnt_root, 1u) == 7u) {
                g_cnt_root = 0u;
                #pragma unroll
                for (int i = 0; i < 8; i++) g_cnt[i] = 0u;
                __threadfence();
                g_bar_sense = next;
            }
        }
        while (g_bar_sense != next) { }
        __threadfence();                       // acquire side
        *sense0 = next;
    }
    __syncthreads();
}

// packed f32x2 fma: d = a*b + d
__device__ __forceinline__ void ffma2(u64& d, u64 a, u64 b) {
    asm("fma.rn.f32x2 %0, %1, %2, %0;" : "+l"(d) : "l"(a), "l"(b));
}
__device__ __forceinline__ float lo32(u64 v) {
    return __uint_as_float((unsigned)(v & 0xFFFFFFFFull));
}
__device__ __forceinline__ float hi32(u64 v) {
    return __uint_as_float((unsigned)(v >> 32));
}
__device__ __forceinline__ u64 pack2(float a, float b) {
    u64 r;
    asm("mov.b64 %0, {%1, %2};" : "=l"(r) : "r"(__float_as_uint(a)), "r"(__float_as_uint(b)));
    return r;
}
__device__ __forceinline__ uint32_t smem_u32(const void* p) {
    uint32_t a;
    asm("{ .reg .u64 t; cvta.to.shared.u64 t, %1; cvt.u32.u64 %0, t; }"
        : "=r"(a) : "l"(p));
    return a;
}
__device__ __forceinline__ void cp16(uint32_t saddr, const void* g) {
    asm volatile("cp.async.ca.shared.global [%0], [%1], 16;"
                 :: "r"(saddr), "l"(g) : "memory");
}
__device__ __forceinline__ void cp_commit() {
    asm volatile("cp.async.commit_group;" ::: "memory");
}
__device__ __forceinline__ void cp_wait0() {
    asm volatile("cp.async.wait_group 0;" ::: "memory");
}

// -------- shared memory (union across phases) --------
struct SmP1 {
    float spw[61 * Dd];     // proj_w (staged per block)
    float spb[Dd];
};
struct SmP2 {
    ulonglong2 buf[2][TCHUNKS];   // [buffer][ sxu(640) | seu(640) ]  = 40KB
};
struct SmP3 {
    float sp[2][4 * PD];    // per-warp Y partials
    float sy[2][PD];        // reduced Y
    float seh[2][HIDh];
    float semb[2][PD];
    float shq[2][SQq];
};
union SmemU {
    SmP1 p1;
    SmP2 p2;
    SmP3 p3;
};

// ============================================================
__global__ void __launch_bounds__(NTHR) fused_all(
        const float* __restrict__ x,
        const float* __restrict__ dc,
        const float* __restrict__ centers,
        const float* __restrict__ proj_w,
        const float* __restrict__ proj_b,
        const float* __restrict__ p_ptr,
        const float* __restrict__ cc,
        const float* __restrict__ gcn_w,
        const float* __restrict__ gcn_b,
        const float* __restrict__ out_w,
        const float* __restrict__ out_b,
        const float* __restrict__ w1,
        const float* __restrict__ b1,
        const float* __restrict__ w2,
        const float* __restrict__ b2,
        float* __restrict__ out) {
    __shared__ SmemU sm;
    __shared__ int slabel[32];
    __shared__ unsigned s_task;

    int tid = threadIdx.x;
    int wid = tid >> 5, lane = tid & 31;
    int bx = blockIdx.x;
    int gt = bx * NTHR + tid;

    unsigned sense0 = 0;
    if (tid == 0) sense0 = g_bar_sense;
    if (gt == 0) g_task = NBLK;     // reset ticket; published by barrier 1

    float p = *p_ptr;
    float c1 = 1.0f - p;

    float* gx = (float*)g_x4;
    float* ge = (float*)g_e4;

    // ======================= P1: prep =======================
    {
        for (int i = tid; i < 61 * Dd; i += NTHR) sm.p1.spw[i] = proj_w[i];
        if (tid < Dd) sm.p1.spb[tid] = proj_b[tid];

        // x mean: one thread per (b,d) row, exact warp-tree order emulation.
        for (int r = gt; r < Bp * Dd; r += NT_ALL) {
            const float4* src = (const float4*)x + (size_t)r * 16;
            float xs[64];
            #pragma unroll
            for (int i = 0; i < 16; i++) {
                float4 a = src[i];
                xs[4 * i]     = a.x;
                xs[4 * i + 1] = a.y;
                xs[4 * i + 2] = a.z;
                xs[4 * i + 3] = a.w;
            }
            float v[32];
            #pragma unroll
            for (int l = 0; l < 32; l++) v[l] = xs[l] + xs[l + 32];
            #pragma unroll
            for (int d = 16; d >= 1; d >>= 1) {
                #pragma unroll
                for (int l = 0; l < 16; l++) {
                    if (l < d) v[l] = v[l] + v[l + d];
                }
            }
            int b = r / Dd, d2 = r - b * Dd;
            gx[b * PD + d2] = v[0] * (1.0f / 64.0f);
        }

        // e = exp(1 - dc) for patients
        for (int idx = gt; idx < Bp * Dd; idx += NT_ALL) {
            int b = idx / Dd, k = idx - b * Dd;
            ge[b * PD + k] = expf(1.0f - dc[idx]);
        }
        // pad slot = 0 for all rows
        for (int i = gt; i < Nn; i += NT_ALL) {
            gx[i * PD + Dd] = 0.0f;
            ge[i * PD + Dd] = 0.0f;
        }

        // centers spread over blocks; sequential-m per-center (bit-exact)
        __syncthreads();   // spw/spb staged
        if ((tid == 0 || tid == 32)) {
            int c = bx + (tid >> 5) * NBLK;   // bx or bx+148
            if (c < NCc) {
                float cp[Dd];
                #pragma unroll
                for (int k = 0; k < Dd; k++) cp[k] = sm.p1.spb[k];
                for (int m = 0; m < 61; m++) {
                    float cm = centers[c * 61 + m];
                    #pragma unroll
                    for (int k = 0; k < Dd; k++) cp[k] += cm * sm.p1.spw[m * Dd + k];
                }
                int row = Bp + c;
                #pragma unroll
                for (int k = 0; k < Dd; k++) {
                    gx[row * PD + k] = cp[k];
                    ge[row * PD + k] = expf(1.0f - cc[c * Dd + k]);
                }
                gx[row * PD + Dd] = 0.0f;
                ge[row * PD + Dd] = 0.0f;
            }
        }
    }

    grid_barrier(&sense0);

    // ===== P2: adjacency + (adj@x) + keys.                           =====
    // ===== Warp = (center-of-8, j-half): 2 unrolled j-iters per warp. =====
    // ===== ONE __syncthreads per task; cp.async double-buffered tile. =====
    {
        const ulonglong2* gxu = (const ulonglong2*)g_x4;
        const ulonglong2* geu = (const ulonglong2*)g_e4;
        int s = lane;
        int wc   = wid & 7;      // center within group of 8
        int half = wid >> 3;     // j-half 0/1

        #define PREFETCH_TILE(tt, pb) do {                                     \
            int _jt = (int)(tt) / NIT;                                         \
            int _j0 = _jt * JT;                                                \
            uint32_t _sb = smem_u32(&sm.p2.buf[(pb)][0]);                      \
            for (int _i = tid; _i < TCHUNKS; _i += NTHR) {                     \
                const void* _src = (_i < JT * PD4)                             \
                    ? (const void*)(gxu + _j0 * PD4 + _i)                      \
                    : (const void*)(geu + _j0 * PD4 + (_i - JT * PD4));        \
                cp16(_sb + _i * 16, _src);                                     \
            }                                                                  \
            cp_commit();                                                       \
        } while (0)

        unsigned t = bx;
        int pb = 0;
        PREFETCH_TILE(t, 0);

        while (t < NTASK) {
            int jt = (int)t / NIT, it = (int)t - ((int)t / NIT) * NIT;
            int j0 = jt * JT;
            bool ptile = (jt < NPJT);

            if (tid == 0) s_task = atomicAdd(&g_task, 1u);

            // center row for this warp (global, ready since barrier 1)
            int cA = it * IT + wc;
            int cgA = Bp + cA;
            ulonglong2 xA[PD4], eA[PD4];
            #pragma unroll
            for (int q = 0; q < PD4; q++) {
                xA[q] = gxu[cgA * PD4 + q];
                eA[q] = geu[cgA * PD4 + q];
            }
            float fxA[PD];
            #pragma unroll
            for (int q = 0; q < PD4; q++) {
                fxA[4 * q]     = lo32(xA[q].x);
                fxA[4 * q + 1] = hi32(xA[q].x);
                fxA[4 * q + 2] = lo32(xA[q].y);
                fxA[4 * q + 3] = hi32(xA[q].y);
            }
            float sqA = 0.0f;
            #pragma unroll
            for (int k = 0; k < Dd; k++) sqA += fxA[k] * fxA[k];

            cp_wait0();          // tile(t) landed (this thread's copies)
            __syncthreads();     // all copies visible; s_task visible;
                                 // previous compute done -> other buffer free
            unsigned t_next = s_task;
            if (t_next < NTASK) PREFETCH_TILE(t_next, pb ^ 1);

            const ulonglong2* bx_ = &sm.p2.buf[pb][0];
            const ulonglong2* be_ = &sm.p2.buf[pb][JT * PD4];

            u64 yA[2 * PD4];
            #pragma unroll
            for (int m = 0; m < 2 * PD4; m++) yA[m] = 0ull;

            // 2 fully-unrolled, independent j-iterations (j-half owned)
            #pragma unroll
            for (int tt = 0; tt < 2; tt++) {
                int j = s + 64 * half + 32 * tt;
                ulonglong2 vv[PD4], ww[PD4];
                #pragma unroll
                for (int q = 0; q < PD4; q++) {
                    vv[q] = bx_[j * PD4 + q];
                    ww[q] = be_[j * PD4 + q];
                }
                // ssq_j: sequential scalar order (bit-exact vs validated)
                float fxJ[PD];
                #pragma unroll
                for (int q = 0; q < PD4; q++) {
                    fxJ[4 * q]     = lo32(vv[q].x);
                    fxJ[4 * q + 1] = hi32(vv[q].x);
                    fxJ[4 * q + 2] = lo32(vv[q].y);
                    fxJ[4 * q + 3] = hi32(vv[q].y);
                }
                float ssqj = 0.0f;
                #pragma unroll
                for (int k = 0; k < Dd; k++) ssqj += fxJ[k] * fxJ[k];

                u64 dxA2 = 0ull, deA2 = 0ull;
                #pragma unroll
                for (int q = 0; q < PD4; q++) {
                    ffma2(dxA2, xA[q].x, vv[q].x);  ffma2(dxA2, xA[q].y, vv[q].y);
                    ffma2(deA2, eA[q].x, ww[q].x);  ffma2(deA2, eA[q].y, ww[q].y);
                }
                float dxA = lo32(dxA2) + hi32(dxA2);
                float deA = lo32(deA2) + hi32(deA2);

                int jg = j0 + j;
                float denA = c1 * (sqA + ssqj - 2.0f * dxA) + p * deA;
                float aA = (jg == cgA) ? 1.0f : __fdividef((float)Dd, denA);

                if (ptile) {
                    // coalesced per-warp key store: [center][patient]
                    g_key[(size_t)cA * Bp + jg] =
                        (((u64)__float_as_uint(denA)) << 32) | (unsigned)cA;
                }

                u64 a2A = pack2(aA, aA);
                #pragma unroll
                for (int q = 0; q < PD4; q++) {
                    ffma2(yA[2 * q],     a2A, vv[q].x);
                    ffma2(yA[2 * q + 1], a2A, vv[q].y);
                }
            }

            // unpack; butterfly -> lane s holds elem s
            float fA[32];
            #pragma unroll
            for (int m = 0; m < 2 * PD4; m++) {
                fA[2 * m] = lo32(yA[m]);  fA[2 * m + 1] = hi32(yA[m]);
            }
            #pragma unroll
            for (int m = 2 * PD; m < 32; m++) fA[m] = 0.0f;
            #pragma unroll
            for (int d = 16; d >= 1; d >>= 1) {
                #pragma unroll
                for (int i = 0; i < d; i++) {
                    float sendA = (s & d) ? fA[i] : fA[i + d];
                    float recvA = __shfl_xor_sync(0xffffffffu, sendA, d);
                    fA[i] = ((s & d) ? fA[i + d] : fA[i]) + recvA;
                }
            }
            if (s < PD) {
                int slot = jt * 2 + half;
                g_party[((size_t)slot * NCc + cA) * PD + s] = fA[0];
            }

            t = t_next;
            pb ^= 1;
        }
        #undef PREFETCH_TILE
    }

    grid_barrier(&sense0);

    // ===== P4a: labels — min over 256 keys/patient (overlaps P3) =====
    if (bx < Bp / 32 && tid < 256) {
        int pl = tid >> 3, l8 = tid & 7;
        int jp = bx * 32 + pl;
        u64 best = 0xFFFFFFFFFFFFFFFFull;
        #pragma unroll 8
        for (int c = l8; c < NCc; c += 8) {
            u64 v = g_key[(size_t)c * Bp + jp];
            if (v < best) best = v;
        }
        u64 o;
        o = __shfl_xor_sync(0xffffffffu, best, 1); if (o < best) best = o;
        o = __shfl_xor_sync(0xffffffffu, best, 2); if (o < best) best = o;
        o = __shfl_xor_sync(0xffffffffu, best, 4); if (o < best) best = o;
        if (l8 == 0) slabel[pl] = (int)(unsigned)(best & 0xFFFFFFFFull);
    }

    // ======================= P3: center MLP chain =======================
    if (wid < 8) {
        int half = wid >> 2;                 // 0/1
        int w4 = wid & 3;
        int c = bx * 2 + half;
        bool active = (bx < NCc / 2);

        float ps = 0.0f;
        if (active && lane < PD) {
            int s0 = w4 * 17;                // 68 slots = 4 x 17
            const float* pp = &g_party[(size_t)c * PD + lane];
            #pragma unroll 17
            for (int sl = s0; sl < s0 + 17; sl++)
                ps += pp[(size_t)sl * (NCc * PD)];
        }
        if (lane < PD) sm.p3.sp[half][w4 * PD + lane] = ps;
    }
    __syncthreads();

    if (wid < 8) {
        int half = wid >> 2;
        int w4 = wid & 3;
        int c = bx * 2 + half;
        bool active = (bx < NCc / 2);

        if (w4 == 0 && active) {
            int h = lane;
            if (lane < PD) {
                const float* spv = sm.p3.sp[half];
                sm.p3.sy[half][lane] = spv[lane] + spv[PD + lane]
                                     + spv[2 * PD + lane] + spv[3 * PD + lane];
            }
            __syncwarp();

            float eh = gcn_b[h];
            #pragma unroll
            for (int k = 0; k < Dd; k++)
                eh += sm.p3.sy[half][k] * gcn_w[k * HIDh + h];
            sm.p3.seh[half][h] = eh;
            __syncwarp();

            if (h < Dd) {
                float v = out_b[h];
                #pragma unroll
                for (int q = 0; q < HIDh; q++) v += sm.p3.seh[half][q] * out_w[q * Dd + h];
                v = 1.0f / (1.0f + expf(-v));
                sm.p3.semb[half][h] = v;
                g_ge[c * Dd + h] = v;
                out[OUT_GE + c * Dd + h] = v;
            }
            __syncwarp();

            if (h < SQq) {
                float v = b1[h];
                #pragma unroll
                for (int k = 0; k < Dd; k++) v += sm.p3.semb[half][k] * w1[k * SQq + h];
                sm.p3.shq[half][h] = 0.5f * v * (1.0f + erff(v * 0.70710678118654752f));
            }
            __syncwarp();

            if (h < Dd) {
                float v = b2[h];
                #pragma unroll
                for (int q = 0; q < SQq; q++) v += sm.p3.shq[half][q] * w2[q * Dd + h];
                g_sc[c * Dd + h] = 1.0f / (1.0f + expf(-v));
            }
        }
    }

    grid_barrier(&sense0);

    // ======================= P4b: gather =======================
    if (bx < Bp / 32 && tid < 256) {
        int pl = tid >> 3, l8 = tid & 7;
        int jp = bx * 32 + pl;
        int label = slabel[pl];
        #pragma unroll
        for (int k = l8; k < Dd; k += 8) {
            out[OUT_GS + jp * Dd + k]  = g_sc[label * Dd + k];
            out[OUT_GPE + jp * Dd + k] = g_ge[label * Dd + k];
        }
        if (l8 == 0) out[OUT_GL + jp] = (float)label;
    }
}

// ============================================================
extern "C" void kernel_launch(void* const* d_in, const int* in_sizes, int n_in,
                              void* d_out, int out_size) {
    const float* x        = (const float*)d_in[0];
    const float* dc       = (const float*)d_in[1];
    const float* centers  = (const float*)d_in[2];
    const float* proj_w   = (const float*)d_in[3];
    const float* proj_b   = (const float*)d_in[4];
    const float* dc_param = (const float*)d_in[5];
    const float* cc       = (const float*)d_in[6];
    const float* gcn_w    = (const float*)d_in[7];
    const float* gcn_b    = (const float*)d_in[8];
    const float* out_w    = (const float*)d_in[9];
    const float* out_b    = (const float*)d_in[10];
    const float* w1       = (const float*)d_in[11];
    const float* b1       = (const float*)d_in[12];
    const float* w2       = (const float*)d_in[13];
    const float* b2       = (const float*)d_in[14];
    float* out = (float*)d_out;

    fused_all<<<NBLK, NTHR>>>(x, dc, centers, proj_w, proj_b, dc_param, cc,
                              gcn_w, gcn_b, out_w, out_b, w1, b1, w2, b2, out);
}

// round 15
// speedup vs baseline: 1.2202x; 1.2202x over previous
#include <cuda_runtime.h>
#include <cstdint>
#include <math.h>

// Problem constants
#define Bp   4096
#define Dd   19
#define Ff   64
#define NCc  256
#define HIDh 32
#define SQq  16
#define Nn   (Bp + NCc)
#define PD   20            // padded row stride (19 + 1 zero pad)
#define PD4  5             // PD/4 (float4 granules)

// P2 tiling: task = (jt, oct of 16 j's). Lane = center. Static 2 tasks/block.
#define JT   128
#define NJT  (Nn / JT)      // 34
#define NPJT (Bp / JT)      // 32 patient-only tiles
#define NTASK (NJT * 8)     // 272 (16-j octants)
#define NSLOT (2 * 148)     // 296 y-partial slots: (block, j-half)

// Persistent grid
#define NBLK 148
#define NTHR 512
#define NT_ALL (NBLK * NTHR)       // 75776

// Output offsets (floats)
#define OUT_GS  0
#define OUT_GE  (Bp * Dd)
#define OUT_GPE ((Bp + NCc) * Dd)
#define OUT_GL  (((2 * Bp) + NCc) * Dd)

typedef unsigned long long u64;

// -------- device scratch (no allocations allowed) --------
__device__ float4 g_x4[Nn * PD4];
__device__ float4 g_e4[Nn * PD4];
__device__ float4 g_party4[NSLOT * NCc * PD4];  // y-partials [slot][center][5]
__device__ u64    g_key[(size_t)Bp * NCc];      // [patient][center] denom keys
__device__ float  g_ge[NCc * Dd];
__device__ float  g_sc[NCc * Dd];

// grid barrier state (zero-init at load; returns to steady state each run)
__device__ unsigned g_cnt[8];
__device__ unsigned g_cnt_root;
__device__ volatile unsigned g_bar_sense;

// Two-level sense-reversal barrier: 8 group counters -> root counter.
__device__ __forceinline__ void grid_barrier(unsigned* sense0) {
    __syncthreads();
    if (threadIdx.x == 0) {
        unsigned next = *sense0 ^ 1u;
        __threadfence();                       // publish this block's writes
        int g = blockIdx.x & 7;
        unsigned gsz = (g < 4) ? 19u : 18u;    // 148 = 4*19 + 4*18
        if (atomicAdd(&g_cnt[g], 1u) == gsz - 1u) {
            if (atomicAdd(&g_cnt_root, 1u) == 7u) {
                g_cnt_root = 0u;
                #pragma unroll
                for (int i = 0; i < 8; i++) g_cnt[i] = 0u;
                __threadfence();
                g_bar_sense = next;
            }
        }
        while (g_bar_sense != next) { }
        __threadfence();                       // acquire side
        *sense0 = next;
    }
    __syncthreads();
}

// packed f32x2 fma: d = a*b + d
__device__ __forceinline__ void ffma2(u64& d, u64 a, u64 b) {
    asm("fma.rn.f32x2 %0, %1, %2, %0;" : "+l"(d) : "l"(a), "l"(b));
}
__device__ __forceinline__ float lo32(u64 v) {
    return __uint_as_float((unsigned)(v & 0xFFFFFFFFull));
}
__device__ __forceinline__ float hi32(u64 v) {
    return __uint_as_float((unsigned)(v >> 32));
}
__device__ __forceinline__ u64 pack2(float a, float b) {
    u64 r;
    asm("mov.b64 %0, {%1, %2};" : "=l"(r) : "r"(__float_as_uint(a)), "r"(__float_as_uint(b)));
    return r;
}
__device__ __forceinline__ uint32_t smem_u32(const void* p) {
    uint32_t a;
    asm("{ .reg .u64 t; cvta.to.shared.u64 t, %1; cvt.u32.u64 %0, t; }"
        : "=r"(a) : "l"(p));
    return a;
}
__device__ __forceinline__ void cp16(uint32_t saddr, const void* g) {
    asm volatile("cp.async.ca.shared.global [%0], [%1], 16;"
                 :: "r"(saddr), "l"(g) : "memory");
}
__device__ __forceinline__ void cp_commit() {
    asm volatile("cp.async.commit_group;" ::: "memory");
}
__device__ __forceinline__ void cp_wait0() {
    asm volatile("cp.async.wait_group 0;" ::: "memory");
}

// -------- shared memory (union across phases) --------
struct SmP1 {
    float spw[61 * Dd];     // proj_w (staged per block)
    float spb[Dd];
};
struct SmP2 {
    // [task 0/1][x(80) | e(80)] 16B chunks: 16 rows x 5 float4 each
    ulonglong2 tile[2][160];
};
struct SmP3 {
    float sp[2][4 * PD];    // per-warp Y partials
    float sy[2][PD];        // reduced Y
    float seh[2][HIDh];
    float semb[2][PD];
    float shq[2][SQq];
};
union SmemU {
    SmP1 p1;
    SmP2 p2;
    SmP3 p3;
};

// ============================================================
__global__ void __launch_bounds__(NTHR) fused_all(
        const float* __restrict__ x,
        const float* __restrict__ dc,
        const float* __restrict__ centers,
        const float* __restrict__ proj_w,
        const float* __restrict__ proj_b,
        const float* __restrict__ p_ptr,
        const float* __restrict__ cc,
        const float* __restrict__ gcn_w,
        const float* __restrict__ gcn_b,
        const float* __restrict__ out_w,
        const float* __restrict__ out_b,
        const float* __restrict__ w1,
        const float* __restrict__ b1,
        const float* __restrict__ w2,
        const float* __restrict__ b2,
        float* __restrict__ out) {
    __shared__ SmemU sm;
    __shared__ int slabel[32];

    int tid = threadIdx.x;
    int wid = tid >> 5, lane = tid & 31;
    int bx = blockIdx.x;
    int gt = bx * NTHR + tid;

    unsigned sense0 = 0;
    if (tid == 0) sense0 = g_bar_sense;

    float p = *p_ptr;
    float c1 = 1.0f - p;

    float* gx = (float*)g_x4;
    float* ge = (float*)g_e4;

    // ======================= P1: prep =======================
    {
        for (int i = tid; i < 61 * Dd; i += NTHR) sm.p1.spw[i] = proj_w[i];
        if (tid < Dd) sm.p1.spb[tid] = proj_b[tid];

        // x mean: one thread per (b,d) row, exact warp-tree order emulation.
        for (int r = gt; r < Bp * Dd; r += NT_ALL) {
            const float4* src = (const float4*)x + (size_t)r * 16;
            float xs[64];
            #pragma unroll
            for (int i = 0; i < 16; i++) {
                float4 a = src[i];
                xs[4 * i]     = a.x;
                xs[4 * i + 1] = a.y;
                xs[4 * i + 2] = a.z;
                xs[4 * i + 3] = a.w;
            }
            float v[32];
            #pragma unroll
            for (int l = 0; l < 32; l++) v[l] = xs[l] + xs[l + 32];
            #pragma unroll
            for (int d = 16; d >= 1; d >>= 1) {
                #pragma unroll
                for (int l = 0; l < 16; l++) {
                    if (l < d) v[l] = v[l] + v[l + d];
                }
            }
            int b = r / Dd, d2 = r - b * Dd;
            gx[b * PD + d2] = v[0] * (1.0f / 64.0f);
        }

        // e = exp(1 - dc) for patients
        for (int idx = gt; idx < Bp * Dd; idx += NT_ALL) {
            int b = idx / Dd, k = idx - b * Dd;
            ge[b * PD + k] = expf(1.0f - dc[idx]);
        }
        // pad slot = 0 for all rows
        for (int i = gt; i < Nn; i += NT_ALL) {
            gx[i * PD + Dd] = 0.0f;
            ge[i * PD + Dd] = 0.0f;
        }

        // centers spread over blocks; sequential-m per-center (bit-exact)
        __syncthreads();   // spw/spb staged
        if ((tid == 0 || tid == 32)) {
            int c = bx + (tid >> 5) * NBLK;   // bx or bx+148
            if (c < NCc) {
                float cp[Dd];
                #pragma unroll
                for (int k = 0; k < Dd; k++) cp[k] = sm.p1.spb[k];
                for (int m = 0; m < 61; m++) {
                    float cm = centers[c * 61 + m];
                    #pragma unroll
                    for (int k = 0; k < Dd; k++) cp[k] += cm * sm.p1.spw[m * Dd + k];
                }
                int row = Bp + c;
                #pragma unroll
                for (int k = 0; k < Dd; k++) {
                    gx[row * PD + k] = cp[k];
                    ge[row * PD + k] = expf(1.0f - cc[c * Dd + k]);
                }
                gx[row * PD + Dd] = 0.0f;
                ge[row * PD + Dd] = 0.0f;
            }
        }
    }

    grid_barrier(&sense0);

    // ===== P2: lane = center (rows in registers, loaded ONCE); =====
    // ===== j-rows broadcast from smem. Static 2 tasks per block. =====
    {
        const ulonglong2* gxu = (const ulonglong2*)g_x4;
        const ulonglong2* geu = (const ulonglong2*)g_e4;
        int wc = wid & 7;        // center group: centers 32*wc + lane
        int jh = wid >> 3;       // j-half of the 16-j octant

        int cA = wc * 32 + lane;
        int cgA = Bp + cA;

        // stage both tasks' 16-row tiles (x and e) via cp.async
        {
            uint32_t sb = smem_u32(&sm.p2.tile[0][0]);
            for (int i = tid; i < 320; i += NTHR) {
                int ti = i / 160, rem = i - ti * 160;
                int which = rem / 80, idx = rem - which * 80;
                int t = bx + ti * NBLK;
                if (t < NTASK) {
                    int jt = t >> 3, oct = t & 7;
                    int grow = jt * JT + oct * 16 + idx / PD4;
                    const void* src = which
                        ? (const void*)(geu + grow * PD4 + (idx % PD4))
                        : (const void*)(gxu + grow * PD4 + (idx % PD4));
                    cp16(sb + (size_t)i * 16, src);
                }
            }
            cp_commit();
        }

        // center rows: registers, once
        ulonglong2 xA[PD4], eA[PD4];
        #pragma unroll
        for (int q = 0; q < PD4; q++) {
            xA[q] = gxu[cgA * PD4 + q];
            eA[q] = geu[cgA * PD4 + q];
        }
        // sqA: sequential scalar order over 19 elements (bit-exact)
        float sqA;
        {
            float fxA[PD];
            #pragma unroll
            for (int q = 0; q < PD4; q++) {
                fxA[4 * q]     = lo32(xA[q].x);
                fxA[4 * q + 1] = hi32(xA[q].x);
                fxA[4 * q + 2] = lo32(xA[q].y);
                fxA[4 * q + 3] = hi32(xA[q].y);
            }
            sqA = 0.0f;
            #pragma unroll
            for (int k = 0; k < Dd; k++) sqA += fxA[k] * fxA[k];
        }

        cp_wait0();
        __syncthreads();

        u64 yA[2 * PD4];
        #pragma unroll
        for (int m = 0; m < 2 * PD4; m++) yA[m] = 0ull;

        #pragma unroll
        for (int ti = 0; ti < 2; ti++) {
            int t = bx + ti * NBLK;
            if (t >= NTASK) break;
            int jt = t >> 3, oct = t & 7;
            bool ptile = (jt < NPJT);
            const ulonglong2* sx = &sm.p2.tile[ti][0];
            const ulonglong2* se = &sm.p2.tile[ti][80];

            #pragma unroll
            for (int jj = 0; jj < 8; jj++) {
                int rj = jh * 8 + jj;                    // row in tile
                int jgg = jt * JT + oct * 16 + rj;       // global row
                ulonglong2 vv[PD4], ww[PD4];
                #pragma unroll
                for (int q = 0; q < PD4; q++) {
                    vv[q] = sx[rj * PD4 + q];            // broadcast LDS
                    ww[q] = se[rj * PD4 + q];
                }
                // ssq_j: sequential scalar order (bit-exact)
                float fxJ[PD];
                #pragma unroll
                for (int q = 0; q < PD4; q++) {
                    fxJ[4 * q]     = lo32(vv[q].x);
                    fxJ[4 * q + 1] = hi32(vv[q].x);
                    fxJ[4 * q + 2] = lo32(vv[q].y);
                    fxJ[4 * q + 3] = hi32(vv[q].y);
                }
                float ssqj = 0.0f;
                #pragma unroll
                for (int k = 0; k < Dd; k++) ssqj += fxJ[k] * fxJ[k];

                u64 dxA2 = 0ull, deA2 = 0ull;
                #pragma unroll
                for (int q = 0; q < PD4; q++) {
                    ffma2(dxA2, xA[q].x, vv[q].x);  ffma2(dxA2, xA[q].y, vv[q].y);
                    ffma2(deA2, eA[q].x, ww[q].x);  ffma2(deA2, eA[q].y, ww[q].y);
                }
                float dxA = lo32(dxA2) + hi32(dxA2);
                float deA = lo32(deA2) + hi32(deA2);

                float denA = c1 * (sqA + ssqj - 2.0f * dxA) + p * deA;
                float aA = (jgg == cgA) ? 1.0f : __fdividef((float)Dd, denA);

                if (ptile) {
                    // coalesced: 32 consecutive centers per warp-store
                    g_key[(size_t)jgg * NCc + cA] =
                        (((u64)__float_as_uint(denA)) << 32) | (unsigned)cA;
                }

                u64 a2A = pack2(aA, aA);
                #pragma unroll
                for (int q = 0; q < PD4; q++) {
                    ffma2(yA[2 * q],     a2A, vv[q].x);
                    ffma2(yA[2 * q + 1], a2A, vv[q].y);
                }
            }
        }

        // one y-partial store per warp-lane: slot = (block, j-half)
        int slot = bx * 2 + jh;
        float4* dst = &g_party4[((size_t)slot * NCc + cA) * PD4];
        #pragma unroll
        for (int q = 0; q < PD4; q++) {
            float4 f;
            f.x = lo32(yA[2 * q]);      f.y = hi32(yA[2 * q]);
            f.z = lo32(yA[2 * q + 1]);  f.w = hi32(yA[2 * q + 1]);
            dst[q] = f;
        }
    }

    grid_barrier(&sense0);

    // ===== P4a: labels — min over 256 contiguous keys/patient (overlaps P3) =====
    if (bx < Bp / 32) {
        // warp w handles patients bx*32 + 2w, +2w+1
        const ulonglong2* gk2 = (const ulonglong2*)g_key;
        #pragma unroll
        for (int pi = 0; pi < 2; pi++) {
            int jp = bx * 32 + wid * 2 + pi;
            u64 best = 0xFFFFFFFFFFFFFFFFull;
            #pragma unroll
            for (int r = 0; r < 4; r++) {
                ulonglong2 kv = gk2[(size_t)jp * 128 + r * 32 + lane];
                u64 m = (kv.x < kv.y) ? kv.x : kv.y;
                if (m < best) best = m;
            }
            u64 o;
            o = __shfl_xor_sync(0xffffffffu, best, 1);  if (o < best) best = o;
            o = __shfl_xor_sync(0xffffffffu, best, 2);  if (o < best) best = o;
            o = __shfl_xor_sync(0xffffffffu, best, 4);  if (o < best) best = o;
            o = __shfl_xor_sync(0xffffffffu, best, 8);  if (o < best) best = o;
            o = __shfl_xor_sync(0xffffffffu, best, 16); if (o < best) best = o;
            if (lane == 0) slabel[wid * 2 + pi] = (int)(unsigned)(best & 0xFFFFFFFFull);
        }
    }

    // ======================= P3: center MLP chain =======================
    if (wid < 8) {
        int half = wid >> 2;                 // 0/1
        int w4 = wid & 3;
        int c = bx * 2 + half;
        bool active = (bx < NCc / 2);

        float ps = 0.0f;
        if (active && lane < PD) {
            int s0 = w4 * 74;                // 296 slots = 4 x 74
            const float* pp = (const float*)g_party4 + (size_t)c * PD + lane;
            for (int sl = s0; sl < s0 + 74; sl++)
                ps += pp[(size_t)sl * (NCc * PD)];
        }
        if (lane < PD) sm.p3.sp[half][w4 * PD + lane] = ps;
    }
    __syncthreads();

    if (wid < 8) {
        int half = wid >> 2;
        int w4 = wid & 3;
        int c = bx * 2 + half;
        bool active = (bx < NCc / 2);

        if (w4 == 0 && active) {
            int h = lane;
            if (lane < PD) {
                const float* spv = sm.p3.sp[half];
                sm.p3.sy[half][lane] = spv[lane] + spv[PD + lane]
                                     + spv[2 * PD + lane] + spv[3 * PD + lane];
            }
            __syncwarp();

            float eh = gcn_b[h];
            #pragma unroll
            for (int k = 0; k < Dd; k++)
                eh += sm.p3.sy[half][k] * gcn_w[k * HIDh + h];
            sm.p3.seh[half][h] = eh;
            __syncwarp();

            if (h < Dd) {
                float v = out_b[h];
                #pragma unroll
                for (int q = 0; q < HIDh; q++) v += sm.p3.seh[half][q] * out_w[q * Dd + h];
                v = 1.0f / (1.0f + expf(-v));
                sm.p3.semb[half][h] = v;
                g_ge[c * Dd + h] = v;
                out[OUT_GE + c * Dd + h] = v;
            }
            __syncwarp();

            if (h < SQq) {
                float v = b1[h];
                #pragma unroll
                for (int k = 0; k < Dd; k++) v += sm.p3.semb[half][k] * w1[k * SQq + h];
                sm.p3.shq[half][h] = 0.5f * v * (1.0f + erff(v * 0.70710678118654752f));
            }
            __syncwarp();

            if (h < Dd) {
                float v = b2[h];
                #pragma unroll
                for (int q = 0; q < SQq; q++) v += sm.p3.shq[half][q] * w2[q * Dd + h];
                g_sc[c * Dd + h] = 1.0f / (1.0f + expf(-v));
            }
        }
    }

    grid_barrier(&sense0);

    // ======================= P4b: gather =======================
    if (bx < Bp / 32 && tid < 256) {
        int pl = tid >> 3, l8 = tid & 7;
        int jp = bx * 32 + pl;
        int label = slabel[pl];
        #pragma unroll
        for (int k = l8; k < Dd; k += 8) {
            out[OUT_GS + jp * Dd + k]  = g_sc[label * Dd + k];
            out[OUT_GPE + jp * Dd + k] = g_ge[label * Dd + k];
        }
        if (l8 == 0) out[OUT_GL + jp] = (float)label;
    }
}

// ============================================================
extern "C" void kernel_launch(void* const* d_in, const int* in_sizes, int n_in,
                              void* d_out, int out_size) {
    const float* x        = (const float*)d_in[0];
    const float* dc       = (const float*)d_in[1];
    const float* centers  = (const float*)d_in[2];
    const float* proj_w   = (const float*)d_in[3];
    const float* proj_b   = (const float*)d_in[4];
    const float* dc_param = (const float*)d_in[5];
    const float* cc       = (const float*)d_in[6];
    const float* gcn_w    = (const float*)d_in[7];
    const float* gcn_b    = (const float*)d_in[8];
    const float* out_w    = (const float*)d_in[9];
    const float* out_b    = (const float*)d_in[10];
    const float* w1       = (const float*)d_in[11];
    const float* b1       = (const float*)d_in[12];
    const float* w2       = (const float*)d_in[13];
    const float* b2       = (const float*)d_in[14];
    float* out = (float*)d_out;

    fused_all<<<NBLK, NTHR>>>(x, dc, centers, proj_w, proj_b, dc_param, cc,
                              gcn_w, gcn_b, out_w, out_b, w1, b1, w2, b2, out);
}